// round 5
// baseline (speedup 1.0000x reference)
#include <cuda_runtime.h>
#include <cstdint>

// Problem constants
#define G   7
#define BSZ 8
#define MSZ 512
#define NSZ 512
#define KSZ 1024
// x zero point = -66, y zero point = 160.
// Sign-flip y: y' = y - 128 (s8). Then:
//   out = s * ( sum(x*y') - 32*sum(x) + 66*sum(y') - 32*66*K )

// GEMM tiling
#define BM 128
#define BN 128
#define BK 64
#define NT (KSZ / BK)   // 16 k-chunks
#define SA 80           // smem row stride in bytes (multiple of 16)

#define XELEMS ((size_t)G * BSZ * MSZ * KSZ)   // 29360128
#define YELEMS ((size_t)BSZ * KSZ * NSZ)       // 4194304

// Scratch (allocation-free: __device__ globals)
__device__ __align__(16) uint8_t g_xp[XELEMS];      // x packed to s8: [g][b][m][k]
__device__ __align__(16) uint8_t g_yt[YELEMS];      // y transposed + sign-flipped: [b][n][k] s8
__device__ int g_Rx[G * BSZ * MSZ];                 // row sums of x (signed)
__device__ int g_Cy[BSZ * NSZ];                     // col sums of y' (signed)
__device__ int g_xfmt;                              // 1 = x given as int32, 0 = raw int8 bytes
__device__ int g_yfmt;                              // 1 = y given as int32, 0 = raw uint8 bytes

// ---------------------------------------------------------------------------
// Kernel 0: probe input encodings. int8-as-int32 means every int32 word is
// in [-128,127] (top 3 bytes = sign extension); random int8 byte-stream
// interpreted as int32 fails this with overwhelming probability.
// ---------------------------------------------------------------------------
__global__ void probe_kernel(const void* x, const void* y) {
    if (threadIdx.x == 0 && blockIdx.x == 0) {
        const int* xi = (const int*)x;
        int ok = 1;
        for (int i = 0; i < 256; i++) { int v = xi[i]; if (v < -128 || v > 127) { ok = 0; break; } }
        g_xfmt = ok;
        const int* yi = (const int*)y;
        ok = 1;
        for (int i = 0; i < 256; i++) { int v = yi[i]; if (v < 0 || v > 255) { ok = 0; break; } }
        g_yfmt = ok;
    }
}

// ---------------------------------------------------------------------------
// Kernel 1: pack x -> s8 (handles int32 or raw-byte input). 16 elems/thread.
// ---------------------------------------------------------------------------
__global__ __launch_bounds__(256) void repack_x_kernel(const void* __restrict__ xin) {
    size_t i = ((size_t)blockIdx.x * 256 + threadIdx.x) * 16;
    if (g_xfmt) {
        const int4* p = (const int4*)xin + (i >> 2);
        uint32_t w[4];
        #pragma unroll
        for (int j = 0; j < 4; j++) {
            int4 v = p[j];
            w[j] = (v.x & 0xff) | ((v.y & 0xff) << 8) | ((v.z & 0xff) << 16) | ((uint32_t)v.w << 24);
        }
        *(uint4*)(g_xp + i) = make_uint4(w[0], w[1], w[2], w[3]);
    } else {
        *(uint4*)(g_xp + i) = ((const uint4*)xin)[i >> 4];
    }
}

// ---------------------------------------------------------------------------
// Kernel 2: transpose y [b][k][n] -> g_yt [b][n][k], pack to s8 (y-128).
// Handles int32 or raw-byte input.
// ---------------------------------------------------------------------------
__global__ __launch_bounds__(256) void transpose_y_kernel(const void* __restrict__ yin) {
    __shared__ __align__(16) uint8_t s[32][136];   // 32 k x 128 n tile, padded rows
    int b  = blockIdx.z;
    int n0 = blockIdx.x * 128;
    int k0 = blockIdx.y * 32;
    int t  = threadIdx.x;
    int fmt = g_yfmt;

    #pragma unroll
    for (int i = 0; i < 4; i++) {
        int w  = t + i * 256;        // 1024 words = 32k x 32 word-of-4n
        int k  = w >> 5;
        int nw = w & 31;
        size_t base = ((size_t)(b * KSZ + k0 + k)) * NSZ + n0 + nw * 4;
        uint32_t wv;
        if (fmt) {
            int4 v = *(const int4*)((const int*)yin + base);
            wv = (v.x & 0xff) | ((v.y & 0xff) << 8) | ((v.z & 0xff) << 16) | ((uint32_t)v.w << 24);
        } else {
            wv = *(const uint32_t*)((const uint8_t*)yin + base);
        }
        *(uint32_t*)&s[k][nw * 4] = wv;
    }
    __syncthreads();
    #pragma unroll
    for (int i = 0; i < 4; i++) {
        int w  = t + i * 256;
        int n  = w >> 3;             // 0..127
        int kq = w & 7;              // 0..7 (4 bytes each)
        uint32_t v = (uint32_t)s[kq * 4 + 0][n]
                   | ((uint32_t)s[kq * 4 + 1][n] << 8)
                   | ((uint32_t)s[kq * 4 + 2][n] << 16)
                   | ((uint32_t)s[kq * 4 + 3][n] << 24);
        v ^= 0x80808080u;            // u8 -> s8 (subtract 128)
        *(uint32_t*)(g_yt + ((size_t)(b * NSZ + n0 + n)) * KSZ + k0 + kq * 4) = v;
    }
}

// ---------------------------------------------------------------------------
// Kernel 3: row sums of packed x (signed bytes), warp per row
// ---------------------------------------------------------------------------
__global__ __launch_bounds__(256) void row_sum_x_kernel() {
    int w = blockIdx.x * 8 + (threadIdx.x >> 5);
    int lane = threadIdx.x & 31;
    const int4* p = (const int4*)(g_xp + (size_t)w * KSZ) + lane;
    int acc = 0;
    #pragma unroll
    for (int i = 0; i < 2; i++) {
        int4 v = p[i * 32];
        acc = __dp4a(v.x, 0x01010101, acc);
        acc = __dp4a(v.y, 0x01010101, acc);
        acc = __dp4a(v.z, 0x01010101, acc);
        acc = __dp4a(v.w, 0x01010101, acc);
    }
    #pragma unroll
    for (int off = 16; off; off >>= 1) acc += __shfl_xor_sync(0xffffffffu, acc, off);
    if (lane == 0) g_Rx[w] = acc;
}

// ---------------------------------------------------------------------------
// Kernel 4: col sums of y' (signed bytes) from g_yt, warp per row
// ---------------------------------------------------------------------------
__global__ __launch_bounds__(256) void row_sum_y_kernel() {
    int w = blockIdx.x * 8 + (threadIdx.x >> 5);
    int lane = threadIdx.x & 31;
    const int4* p = (const int4*)(g_yt + (size_t)w * KSZ) + lane;
    int acc = 0;
    #pragma unroll
    for (int i = 0; i < 2; i++) {
        int4 v = p[i * 32];
        acc = __dp4a(v.x, 0x01010101, acc);
        acc = __dp4a(v.y, 0x01010101, acc);
        acc = __dp4a(v.z, 0x01010101, acc);
        acc = __dp4a(v.w, 0x01010101, acc);
    }
    #pragma unroll
    for (int off = 16; off; off >>= 1) acc += __shfl_xor_sync(0xffffffffu, acc, off);
    if (lane == 0) g_Cy[w] = acc;
}

// ---------------------------------------------------------------------------
// Kernel 5: s8 x s8 -> s32 GEMM, 128x128x64 tiles, cp.async double buffer,
//           mma.sync m16n8k32 s8.s8, integer-exact epilogue.
// ---------------------------------------------------------------------------
__global__ __launch_bounds__(256) void gemm_kernel(const float* __restrict__ xs,
                                                   const float* __restrict__ ys,
                                                   float* __restrict__ out) {
    __shared__ __align__(16) uint8_t As[2][BM * SA];
    __shared__ __align__(16) uint8_t Bs[2][BN * SA];

    const int t  = threadIdx.x;
    const int z  = blockIdx.z;      // g*8 + b
    const int b  = z & 7;
    const int m0 = blockIdx.y * BM;
    const int n0 = blockIdx.x * BN;
    const int warp = t >> 5, lane = t & 31;
    const int wm = warp >> 2, wn = warp & 3;     // warps 2(m) x 4(n); warp tile 64x32
    const int lr = lane >> 2, lc = lane & 3;

    const uint8_t* xa = g_xp + (size_t)z * MSZ * KSZ + (size_t)m0 * KSZ;
    const uint8_t* yb = g_yt + (size_t)b * NSZ * KSZ + (size_t)n0 * KSZ;

    int acc[4][4][4];
    #pragma unroll
    for (int i = 0; i < 4; i++)
        #pragma unroll
        for (int j = 0; j < 4; j++)
            #pragma unroll
            for (int r = 0; r < 4; r++) acc[i][j][r] = 0;

    auto load_chunk = [&](int kt, int buf) {
        int k0 = kt * BK;
        #pragma unroll
        for (int i = 0; i < 2; i++) {
            int id  = t + i * 256;          // 512 int4 per tile
            int row = id >> 2;
            int col = (id & 3) << 4;
            unsigned da = (unsigned)__cvta_generic_to_shared(&As[buf][row * SA + col]);
            asm volatile("cp.async.cg.shared.global [%0], [%1], 16;\n"
                         :: "r"(da), "l"(xa + (size_t)row * KSZ + k0 + col));
            unsigned db = (unsigned)__cvta_generic_to_shared(&Bs[buf][row * SA + col]);
            asm volatile("cp.async.cg.shared.global [%0], [%1], 16;\n"
                         :: "r"(db), "l"(yb + (size_t)row * KSZ + k0 + col));
        }
        asm volatile("cp.async.commit_group;\n");
    };

    load_chunk(0, 0);

    for (int kt = 0; kt < NT; ++kt) {
        const int buf = kt & 1;
        if (kt + 1 < NT) {
            load_chunk(kt + 1, buf ^ 1);
            asm volatile("cp.async.wait_group 1;\n");
        } else {
            asm volatile("cp.async.wait_group 0;\n");
        }
        __syncthreads();

        const uint8_t* A  = As[buf];
        const uint8_t* Bp = Bs[buf];
        #pragma unroll
        for (int ks = 0; ks < BK; ks += 32) {
            int a[4][4], bb[4][2];
            #pragma unroll
            for (int mf = 0; mf < 4; mf++) {
                const uint8_t* ap = A + (wm * 64 + mf * 16 + lr) * SA + ks + lc * 4;
                a[mf][0] = *(const int*)(ap);
                a[mf][1] = *(const int*)(ap + 8 * SA);
                a[mf][2] = *(const int*)(ap + 16);
                a[mf][3] = *(const int*)(ap + 8 * SA + 16);
            }
            #pragma unroll
            for (int nf = 0; nf < 4; nf++) {
                const uint8_t* bp = Bp + (wn * 32 + nf * 8 + lr) * SA + ks + lc * 4;
                bb[nf][0] = *(const int*)(bp);
                bb[nf][1] = *(const int*)(bp + 16);
            }
            #pragma unroll
            for (int mf = 0; mf < 4; mf++)
                #pragma unroll
                for (int nf = 0; nf < 4; nf++) {
                    asm volatile(
                        "mma.sync.aligned.m16n8k32.row.col.s32.s8.s8.s32 "
                        "{%0,%1,%2,%3}, {%4,%5,%6,%7}, {%8,%9}, {%0,%1,%2,%3};"
                        : "+r"(acc[mf][nf][0]), "+r"(acc[mf][nf][1]),
                          "+r"(acc[mf][nf][2]), "+r"(acc[mf][nf][3])
                        : "r"(a[mf][0]), "r"(a[mf][1]), "r"(a[mf][2]), "r"(a[mf][3]),
                          "r"(bb[nf][0]), "r"(bb[nf][1]));
                }
        }
        __syncthreads();
    }

    // Epilogue: out = s * ( dot' - 32*Rx + 66*Cy' - 32*66*K )
    const float s = xs[0] * ys[0];
    const int C0 = -32 * 66 * KSZ;   // -2162688
    #pragma unroll
    for (int mf = 0; mf < 4; mf++) {
        int gm0 = m0 + wm * 64 + mf * 16 + lr;
        int rx0 = g_Rx[z * MSZ + gm0];
        int rx1 = g_Rx[z * MSZ + gm0 + 8];
        #pragma unroll
        for (int nf = 0; nf < 4; nf++) {
            int gn  = n0 + wn * 32 + nf * 8 + lc * 2;
            int cy0 = g_Cy[b * NSZ + gn];
            int cy1 = g_Cy[b * NSZ + gn + 1];
            float2 v0, v1;
            v0.x = s * (float)(acc[mf][nf][0] - 32 * rx0 + 66 * cy0 + C0);
            v0.y = s * (float)(acc[mf][nf][1] - 32 * rx0 + 66 * cy1 + C0);
            v1.x = s * (float)(acc[mf][nf][2] - 32 * rx1 + 66 * cy0 + C0);
            v1.y = s * (float)(acc[mf][nf][3] - 32 * rx1 + 66 * cy1 + C0);
            *(float2*)(out + ((size_t)z * MSZ + gm0) * NSZ + gn)     = v0;
            *(float2*)(out + ((size_t)z * MSZ + gm0 + 8) * NSZ + gn) = v1;
        }
    }
}

// ---------------------------------------------------------------------------
// kernel_launch: identify inputs BY SIZE (element counts).
// ---------------------------------------------------------------------------
extern "C" void kernel_launch(void* const* d_in, const int* in_sizes, int n_in,
                              void* d_out, int out_size) {
    const void* x  = nullptr;
    const void* y  = nullptr;
    const float* xs = nullptr;
    const float* ys = nullptr;

    for (int i = 0; i < n_in; i++) {
        long sz = in_sizes[i];
        if (sz == (long)XELEMS) {
            x = d_in[i];
        } else if (sz == (long)YELEMS) {
            y = d_in[i];
        } else {
            if (xs == nullptr) xs = (const float*)d_in[i];
            else if (ys == nullptr) ys = (const float*)d_in[i];
        }
    }
    float* out = (float*)d_out;

    // 0) detect int32 vs raw-byte encodings
    probe_kernel<<<1, 32>>>(x, y);
    // 1) pack x -> s8
    repack_x_kernel<<<(int)(XELEMS / (16 * 256)), 256>>>(x);
    // 2) transpose + sign-flip y -> [b][n][k] s8
    transpose_y_kernel<<<dim3(NSZ / 128, KSZ / 32, BSZ), 256>>>(y);
    // 3) row sums of packed x
    row_sum_x_kernel<<<(G * BSZ * MSZ) / 8, 256>>>();
    // 4) col sums of y'
    row_sum_y_kernel<<<(BSZ * NSZ) / 8, 256>>>();
    // 5) integer GEMM + fused dequant epilogue
    gemm_kernel<<<dim3(NSZ / BN, MSZ / BM, G * BSZ), 256>>>(xs, ys, out);
}

// round 8
// speedup vs baseline: 2.3585x; 2.3585x over previous
#include <cuda_runtime.h>
#include <cuda_bf16.h>
#include <cstdint>

// Problem constants
#define G   7
#define BSZ 8
#define MSZ 512
#define NSZ 512
#define KSZ 1024
// x zp = -66, y zp = 160. Sign-flip y: y' = y - 128. Then
//   out = s * ( sum(x*y') - 32*sum(x) + 66*sum(y') - 32*66*K )
#define C0F (-2162688.0f)   // -32*66*1024

#define XELEMS ((size_t)G * BSZ * MSZ * KSZ)   // 29360128
#define YELEMS ((size_t)BSZ * KSZ * NSZ)       // 4194304

// ---- arch-specific feature gate (tcgen05 only legal on sm_103a pass) ----
#if defined(__CUDA_ARCH_FEAT_SM103_ALL) || \
    (defined(__CUDA_ARCH_SPECIFIC__) && (__CUDA_ARCH_SPECIFIC__ == 1030)) || \
    (defined(__CUDA_ARCH_FAMILY_SPECIFIC__) && (__CUDA_ARCH_FAMILY_SPECIFIC__ == 1030))
#define TC_OK 1
#endif

// ---------------- tcgen05 bf16 GEMM tiling ----------------
#define BMG 128
#define BNG 256
#define BKE 64              // K elements per stage (128 bytes bf16 per row)
#define NSTG (KSZ / BKE)    // 16
#define SM_A(buf)  ((buf) * 16384)            // 2 x 16KB  (128 rows x 128B)
#define SM_B(buf)  (32768 + (buf) * 32768)    // 2 x 32KB  (256 rows x 128B)
#define SM_TMEMP   98304
#define SM_MBAR0   98312
#define SM_MBAR1   98320
#define SM_RXS     98336                      // 128 x float (32*Rx)
#define SM_CYS     98848                      // 256 x float (66*Cy + C0)
#define DSMEM_TC   99872

// Scratch (allocation-free: __device__ globals)
__device__ __align__(16) uint16_t g_xb[XELEMS];   // x as bf16 [z][m][k]
__device__ __align__(16) uint16_t g_ytb[YELEMS];  // y' transposed bf16 [b][n][k]
__device__ int   g_Rx[G * BSZ * MSZ];
__device__ float g_CyF[BSZ * NSZ];
__device__ int g_xfmt;
__device__ int g_yfmt;

// ---------------------------------------------------------------------------
// helpers
// ---------------------------------------------------------------------------
__device__ __forceinline__ uint32_t smem_u32(const void* p) {
    uint32_t a;
    asm("{ .reg .u64 t; cvta.to.shared.u64 t, %1; cvt.u32.u64 %0, t; }" : "=r"(a) : "l"(p));
    return a;
}
__device__ __forceinline__ void cp16(uint32_t dst, const void* src) {
    asm volatile("cp.async.cg.shared.global [%0], [%1], 16;" :: "r"(dst), "l"(src));
}
__device__ __forceinline__ uint32_t pack_bf16(float lo, float hi) {
    __nv_bfloat162 h = __floats2bfloat162_rn(lo, hi);
    return *(uint32_t*)&h;
}

// ---------------------------------------------------------------------------
// Kernel 0: probe input encodings (int32-materialized vs raw bytes)
// ---------------------------------------------------------------------------
__global__ void probe_kernel(const void* x, const void* y) {
    if (threadIdx.x == 0 && blockIdx.x == 0) {
        const int* xi = (const int*)x;
        int ok = 1;
        for (int i = 0; i < 256; i++) { int v = xi[i]; if (v < -128 || v > 127) { ok = 0; break; } }
        g_xfmt = ok;
        const int* yi = (const int*)y;
        ok = 1;
        for (int i = 0; i < 256; i++) { int v = yi[i]; if (v < 0 || v > 255) { ok = 0; break; } }
        g_yfmt = ok;
    }
}

// ---------------------------------------------------------------------------
// Kernel 1: x -> bf16 AND row sums (fused). Warp per row (1024 elems).
// ---------------------------------------------------------------------------
__global__ __launch_bounds__(256) void repack_rowsum_x(const void* __restrict__ xin) {
    int row  = blockIdx.x * 8 + (threadIdx.x >> 5);
    int lane = threadIdx.x & 31;
    int acc = 0;
    if (g_xfmt) {
        const int4* src = (const int4*)xin + (size_t)row * (KSZ / 4);
        #pragma unroll
        for (int i = 0; i < 4; i++) {
            int c = lane + i * 32;               // 8-elem chunk, 0..127
            int4 v0 = src[c * 2], v1 = src[c * 2 + 1];
            acc += v0.x + v0.y + v0.z + v0.w + v1.x + v1.y + v1.z + v1.w;
            uint4 o;
            o.x = pack_bf16((float)v0.x, (float)v0.y);
            o.y = pack_bf16((float)v0.z, (float)v0.w);
            o.z = pack_bf16((float)v1.x, (float)v1.y);
            o.w = pack_bf16((float)v1.z, (float)v1.w);
            *(uint4*)(g_xb + (size_t)row * KSZ + c * 8) = o;
        }
    } else {
        const uint8_t* src = (const uint8_t*)xin + (size_t)row * KSZ;
        #pragma unroll
        for (int i = 0; i < 4; i++) {
            int c = lane + i * 32;
            uint2 v = *(const uint2*)(src + c * 8);
            int e[8];
            #pragma unroll
            for (int j = 0; j < 4; j++) e[j]     = (int)(int8_t)(v.x >> (8 * j));
            #pragma unroll
            for (int j = 0; j < 4; j++) e[4 + j] = (int)(int8_t)(v.y >> (8 * j));
            #pragma unroll
            for (int j = 0; j < 8; j++) acc += e[j];
            uint4 o;
            o.x = pack_bf16((float)e[0], (float)e[1]);
            o.y = pack_bf16((float)e[2], (float)e[3]);
            o.z = pack_bf16((float)e[4], (float)e[5]);
            o.w = pack_bf16((float)e[6], (float)e[7]);
            *(uint4*)(g_xb + (size_t)row * KSZ + c * 8) = o;
        }
    }
    #pragma unroll
    for (int off = 16; off; off >>= 1) acc += __shfl_xor_sync(0xffffffffu, acc, off);
    if (lane == 0) g_Rx[row] = acc;
}

// ---------------------------------------------------------------------------
// Kernel 2: transpose y [b][k][n] -> g_ytb [b][n][k], bf16 of (y-128)
// ---------------------------------------------------------------------------
__global__ __launch_bounds__(256) void transpose_y_kernel(const void* __restrict__ yin) {
    __shared__ __align__(16) uint8_t s[32][136];
    int b  = blockIdx.z;
    int n0 = blockIdx.x * 128;
    int k0 = blockIdx.y * 32;
    int t  = threadIdx.x;
    int fmt = g_yfmt;

    #pragma unroll
    for (int i = 0; i < 4; i++) {
        int w  = t + i * 256;
        int k  = w >> 5;
        int nw = w & 31;
        size_t base = ((size_t)(b * KSZ + k0 + k)) * NSZ + n0 + nw * 4;
        uint32_t wv;
        if (fmt) {
            int4 v = *(const int4*)((const int*)yin + base);
            wv = (v.x & 0xff) | ((v.y & 0xff) << 8) | ((v.z & 0xff) << 16) | ((uint32_t)(v.w & 0xff) << 24);
        } else {
            wv = *(const uint32_t*)((const uint8_t*)yin + base);
        }
        *(uint32_t*)&s[k][nw * 4] = wv;
    }
    __syncthreads();
    #pragma unroll
    for (int i = 0; i < 4; i++) {
        int w  = t + i * 256;
        int n  = w >> 3;
        int kq = w & 7;
        int e0 = (int)s[kq * 4 + 0][n] - 128;
        int e1 = (int)s[kq * 4 + 1][n] - 128;
        int e2 = (int)s[kq * 4 + 2][n] - 128;
        int e3 = (int)s[kq * 4 + 3][n] - 128;
        uint2 o;
        o.x = pack_bf16((float)e0, (float)e1);
        o.y = pack_bf16((float)e2, (float)e3);
        *(uint2*)(g_ytb + ((size_t)(b * NSZ + n0 + n)) * KSZ + k0 + kq * 4) = o;
    }
}

// ---------------------------------------------------------------------------
// Kernel 3: col sums of y' from g_ytb (bf16), warp per row; store 66*cy+C0
// ---------------------------------------------------------------------------
__global__ __launch_bounds__(256) void col_sum_y_kernel() {
    int w = blockIdx.x * 8 + (threadIdx.x >> 5);
    int lane = threadIdx.x & 31;
    const uint4* p = (const uint4*)(g_ytb + (size_t)w * KSZ);
    float acc = 0.f;
    #pragma unroll
    for (int i = 0; i < 4; i++) {
        uint4 v = p[lane + i * 32];
        const uint32_t* vv = (const uint32_t*)&v;
        #pragma unroll
        for (int j = 0; j < 4; j++) {
            float2 f = __bfloat1622float2(*(const __nv_bfloat162*)&vv[j]);
            acc += f.x + f.y;
        }
    }
    #pragma unroll
    for (int off = 16; off; off >>= 1) acc += __shfl_xor_sync(0xffffffffu, acc, off);
    if (lane == 0) g_CyF[w] = 66.0f * acc + C0F;
}

// ---------------------------------------------------------------------------
// Kernel 4: tcgen05 bf16 GEMM. CTA tile 128(M) x 256(N), fp32 accum in TMEM.
// ---------------------------------------------------------------------------
#ifdef TC_OK
__device__ __forceinline__ uint32_t sw128(uint32_t off) { return off ^ ((off >> 3) & 0x70); }
__device__ __forceinline__ uint32_t elect_one() {
    uint32_t p;
    asm volatile("{\n\t.reg .pred P;\n\telect.sync _|P, 0xFFFFFFFF;\n\tselp.b32 %0, 1, 0, P;\n\t}" : "=r"(p));
    return p;
}
__device__ __forceinline__ void mbar_init(uint32_t a, uint32_t cnt) {
    asm volatile("mbarrier.init.shared.b64 [%0], %1;" :: "r"(a), "r"(cnt) : "memory");
}
__device__ __forceinline__ void mbar_wait(uint32_t a, uint32_t parity) {
    asm volatile(
        "{\n\t.reg .pred P;\n\t"
        "W%=:\n\t"
        "mbarrier.try_wait.parity.acquire.cta.shared::cta.b64 P, [%0], %1, 0x989680;\n\t"
        "@P bra D%=;\n\t"
        "bra W%=;\n\t"
        "D%=:\n\t}"
        :: "r"(a), "r"(parity) : "memory");
}
__device__ __forceinline__ uint64_t smem_desc(uint32_t addr) {
    const uint64_t base = (uint64_t(2) << 61) | (uint64_t(1) << 46) | (uint64_t(64) << 32) | (uint64_t(1) << 16);
    return base | ((uint64_t)(addr >> 4) & 0x3FFF);
}
// idesc kind::f16: dtype F32(1)<<4, atype BF16(1)<<7, btype BF16(1)<<10,
//                  (N/8)<<17, (M/16)<<24  -> 0x08400490 for M=128,N=256
#define IDESC_F16 ((1u << 4) | (1u << 7) | (1u << 10) | ((BNG / 8) << 17) | ((BMG / 16) << 24))
__device__ __forceinline__ void mma_bf16(uint32_t d, uint64_t ad, uint64_t bd, uint32_t en) {
    asm volatile(
        "{\n\t.reg .pred p;\n\tsetp.ne.u32 p, %5, 0;\n\t"
        "tcgen05.mma.cta_group::1.kind::f16 [%0], %1, %2, %3, {%4, %4, %4, %4}, p;\n\t}"
        :: "r"(d), "l"(ad), "l"(bd), "r"((uint32_t)IDESC_F16), "r"(0u), "r"(en) : "memory");
}
#endif

__global__ __launch_bounds__(128, 2) void gemm_tc(const float* __restrict__ xs,
                                                  const float* __restrict__ ys,
                                                  float* __restrict__ out) {
#ifdef TC_OK
    extern __shared__ __align__(1024) uint8_t smem[];
    const uint32_t sb = smem_u32(smem);
    const int t = threadIdx.x, wid = t >> 5, lane = t & 31;
    const int z = blockIdx.z, b = z & 7;
    const int m0 = blockIdx.y * BMG;
    const int n0 = blockIdx.x * BNG;

    if (wid == 0) {
        asm volatile("tcgen05.alloc.cta_group::1.sync.aligned.shared::cta.b32 [%0], %1;"
                     :: "r"(sb + SM_TMEMP), "r"(256u) : "memory");
        asm volatile("tcgen05.relinquish_alloc_permit.cta_group::1.sync.aligned;" ::: "memory");
    }
    if (t == 0) { mbar_init(sb + SM_MBAR0, 1); mbar_init(sb + SM_MBAR1, 1); }
    __syncthreads();
    uint32_t tmem;
    asm volatile("ld.shared.b32 %0, [%1];" : "=r"(tmem) : "r"(sb + SM_TMEMP));

    const uint16_t* xa = g_xb  + (size_t)z * MSZ * KSZ + (size_t)m0 * KSZ;
    const uint16_t* yb = g_ytb + (size_t)b * NSZ * KSZ + (size_t)n0 * KSZ;

    auto loadstage = [&](int s, int buf) {
        uint32_t ab = sb + SM_A(buf);
        uint32_t bbse = sb + SM_B(buf);
        #pragma unroll
        for (int i = 0; i < 8; i++) {          // A: 128 rows x 128B
            int id = t + i * 128;
            int row = id >> 3, c = (id & 7) << 4;      // byte col 0..112
            cp16(ab + sw128(row * 128 + c), (const uint8_t*)(xa + (size_t)row * KSZ + s * BKE) + c);
        }
        #pragma unroll
        for (int i = 0; i < 16; i++) {         // B: 256 rows x 128B
            int id = t + i * 128;
            int row = id >> 3, c = (id & 7) << 4;
            cp16(bbse + sw128(row * 128 + c), (const uint8_t*)(yb + (size_t)row * KSZ + s * BKE) + c);
        }
        asm volatile("cp.async.commit_group;" ::: "memory");
    };

    int ph0 = 0, ph1 = 0;
    loadstage(0, 0);

    for (int s = 0; s < NSTG; s++) {
        const int buf = s & 1;
        if (s + 1 < NSTG) {
            const int nb = buf ^ 1;
            if (s + 1 >= 2) {    // nb was consumed by mma of stage s-1
                if (nb == 0) { mbar_wait(sb + SM_MBAR0, ph0); ph0 ^= 1; }
                else         { mbar_wait(sb + SM_MBAR1, ph1); ph1 ^= 1; }
            }
            loadstage(s + 1, nb);
            asm volatile("cp.async.wait_group 1;" ::: "memory");
        } else {
            asm volatile("cp.async.wait_group 0;" ::: "memory");
        }
        __syncthreads();
        asm volatile("fence.proxy.async.shared::cta;" ::: "memory");

        if (wid == 0) {
            asm volatile("tcgen05.fence::after_thread_sync;" ::: "memory");
            if (elect_one()) {
                uint64_t ad = smem_desc(sb + SM_A(buf));
                uint64_t bd = smem_desc(sb + SM_B(buf));
                #pragma unroll
                for (int k = 0; k < 4; k++)    // 4 x K=16 dispatches per 128B stage
                    mma_bf16(tmem, ad + k * 2, bd + k * 2, (uint32_t)(s * 4 + k));
                asm volatile("tcgen05.commit.cta_group::1.mbarrier::arrive::one.shared::cluster.b64 [%0];"
                             :: "r"(sb + (buf ? SM_MBAR1 : SM_MBAR0)) : "memory");
            }
        }
    }

    // stage 15 used buf1; its commit tracks all prior mma work
    mbar_wait(sb + SM_MBAR1, ph1);
    asm volatile("tcgen05.fence::after_thread_sync;" ::: "memory");

    // preload corrections
    float* rxs = (float*)(smem + SM_RXS);   // 32*Rx
    float* cys = (float*)(smem + SM_CYS);   // 66*Cy + C0
    rxs[t] = 32.0f * (float)g_Rx[z * MSZ + m0 + t];
    cys[t]       = g_CyF[b * NSZ + n0 + t];
    cys[t + 128] = g_CyF[b * NSZ + n0 + 128 + t];
    __syncthreads();

    const float sc = xs[0] * ys[0];
    const float rx32 = rxs[wid * 32 + lane];
    float* tile = (float*)(smem + wid * 4352);  // per-warp 32x33 f32 transpose tile

    #pragma unroll 1
    for (int chunk = 0; chunk < BNG / 32; chunk++) {
        uint32_t d[32];
        asm volatile(
            "tcgen05.ld.sync.aligned.32x32b.x32.b32 "
            "{%0,%1,%2,%3,%4,%5,%6,%7,%8,%9,%10,%11,%12,%13,%14,%15,"
            "%16,%17,%18,%19,%20,%21,%22,%23,%24,%25,%26,%27,%28,%29,%30,%31}, [%32];"
            : "=r"(d[0]), "=r"(d[1]), "=r"(d[2]), "=r"(d[3]), "=r"(d[4]), "=r"(d[5]), "=r"(d[6]), "=r"(d[7]),
              "=r"(d[8]), "=r"(d[9]), "=r"(d[10]), "=r"(d[11]), "=r"(d[12]), "=r"(d[13]), "=r"(d[14]), "=r"(d[15]),
              "=r"(d[16]), "=r"(d[17]), "=r"(d[18]), "=r"(d[19]), "=r"(d[20]), "=r"(d[21]), "=r"(d[22]), "=r"(d[23]),
              "=r"(d[24]), "=r"(d[25]), "=r"(d[26]), "=r"(d[27]), "=r"(d[28]), "=r"(d[29]), "=r"(d[30]), "=r"(d[31])
            : "r"(tmem + chunk * 32));
        asm volatile("tcgen05.wait::ld.sync.aligned;" ::: "memory");

        #pragma unroll
        for (int c = 0; c < 32; c++) {
            float fd = __uint_as_float(d[c]);
            tile[lane * 33 + c] = sc * (fd - rx32 + cys[chunk * 32 + c]);
        }
        __syncwarp();
        #pragma unroll
        for (int r = 0; r < 32; r++) {
            out[((size_t)z * MSZ + m0 + wid * 32 + r) * NSZ + n0 + chunk * 32 + lane] = tile[r * 33 + lane];
        }
        __syncwarp();
    }

    __syncthreads();
    if (wid == 0) {
        asm volatile("tcgen05.dealloc.cta_group::1.sync.aligned.b32 %0, %1;" :: "r"(tmem), "r"(256u));
    }
#endif
}

// ---------------------------------------------------------------------------
extern "C" void kernel_launch(void* const* d_in, const int* in_sizes, int n_in,
                              void* d_out, int out_size) {
    const void* x = nullptr;
    const void* y = nullptr;
    const float* xs = nullptr;
    const float* ys = nullptr;

    for (int i = 0; i < n_in; i++) {
        long sz = in_sizes[i];
        if (sz == (long)XELEMS) x = d_in[i];
        else if (sz == (long)YELEMS) y = d_in[i];
        else if (xs == nullptr) xs = (const float*)d_in[i];
        else if (ys == nullptr) ys = (const float*)d_in[i];
    }
    float* out = (float*)d_out;

    cudaFuncSetAttribute(gemm_tc, cudaFuncAttributeMaxDynamicSharedMemorySize, DSMEM_TC);

    probe_kernel<<<1, 32>>>(x, y);
    repack_rowsum_x<<<(G * BSZ * MSZ) / 8, 256>>>(x);
    transpose_y_kernel<<<dim3(NSZ / 128, KSZ / 32, BSZ), 256>>>(y);
    col_sum_y_kernel<<<(BSZ * NSZ) / 8, 256>>>();
    gemm_tc<<<dim3(NSZ / BNG, MSZ / BMG, G * BSZ), 128, DSMEM_TC>>>(xs, ys, out);
}